// round 15
// baseline (speedup 1.0000x reference)
#include <cuda_runtime.h>
#include <cuda_bf16.h>
#include <math.h>
#include <stdint.h>

// Problem constants
#define B_SZ    4096
#define D_SZ    768
#define HID_SZ  256
#define NC_SZ   200
#define NOLD_SZ 100
#define NNEW_SZ 100
#define EPSILONF 0.05f
#define INV_TAU  10.0f
#define EPSF     1e-8f
#define SIM_TILES 528            // 32*33/2 upper-tri 128x128 tiles

// ---------------- device scratch (static: no allocations allowed) -------------
__device__ __nv_bfloat16 g_znorm16[B_SZ * D_SZ];
__device__ __nv_bfloat16 g_bnorm16[B_SZ * D_SZ];
__device__ __nv_bfloat16 g_f1z16[B_SZ * HID_SZ];
__device__ __nv_bfloat16 g_f2z16[B_SZ * HID_SZ];
__device__ float g_sim[(size_t)B_SZ * B_SZ];
__device__ float g_attn[(size_t)B_SZ * B_SZ];
__device__ unsigned char g_mask[(size_t)B_SZ * B_SZ];
__device__ float g_meanprobs[NC_SZ];
__device__ float g_losssum;
__device__ float g_nvalid;

// ---------------- helpers -------------------------------------------------------
__device__ __forceinline__ float to_tf32(float x) {
    float y;
    asm("cvt.rna.tf32.f32 %0, %1;" : "=f"(y) : "f"(x));
    return y;
}
#define CP_ASYNC16(dst, src) \
    asm volatile("cp.async.cg.shared.global [%0], [%1], 16;" :: "r"(dst), "l"(src) : "memory")
#define CP_COMMIT() asm volatile("cp.async.commit_group;" ::: "memory")
#define CP_WAIT2()  asm volatile("cp.async.wait_group 2;" ::: "memory")

__device__ __forceinline__ uint32_t smem_u32(const void* p) {
    uint32_t a;
    asm("{ .reg .u64 t; cvta.to.shared.u64 t, %1; cvt.u32.u64 %0, t; }" : "=r"(a) : "l"(p));
    return a;
}
__device__ __forceinline__ void mma_tf32(float* d, const uint32_t* a, const uint32_t* b) {
    asm volatile(
        "mma.sync.aligned.m16n8k8.row.col.f32.tf32.tf32.f32 "
        "{%0,%1,%2,%3}, {%4,%5,%6,%7}, {%8,%9}, {%0,%1,%2,%3};"
        : "+f"(d[0]), "+f"(d[1]), "+f"(d[2]), "+f"(d[3])
        : "r"(a[0]), "r"(a[1]), "r"(a[2]), "r"(a[3]), "r"(b[0]), "r"(b[1]));
}
__device__ __forceinline__ void mma_bf16(float* d, const uint32_t* a, const uint32_t* b) {
    asm volatile(
        "mma.sync.aligned.m16n8k16.row.col.f32.bf16.bf16.f32 "
        "{%0,%1,%2,%3}, {%4,%5,%6,%7}, {%8,%9}, {%0,%1,%2,%3};"
        : "+f"(d[0]), "+f"(d[1]), "+f"(d[2]), "+f"(d[3])
        : "r"(a[0]), "r"(a[1]), "r"(a[2]), "r"(a[3]), "r"(b[0]), "r"(b[1]));
}

// exp(10*s) on the FMA/ALU pipes (no MUFU)
__device__ __forceinline__ float exp10s_poly(float s) {
    float x = s * 14.426950408889634f;
    float kf = rintf(x);
    float l = (x - kf) * 0.6931471805599453f;
    float p = fmaf(l, 1.0f / 120.0f, 1.0f / 24.0f);
    p = fmaf(p, l, 1.0f / 6.0f);
    p = fmaf(p, l, 0.5f);
    p = fmaf(p, l, 1.0f);
    p = fmaf(p, l, 1.0f);
    int ik = (int)kf;
    return __int_as_float(__float_as_int(p) + (ik << 23));
}

// ---------------- init ---------------------------------------------------------
__global__ void zero_kernel() {
    int t = threadIdx.x;
    if (t < NC_SZ) g_meanprobs[t] = 0.f;
    if (t == 0) { g_losssum = 0.f; g_nvalid = 0.f; }
}

// ---------------- entropy stats -------------------------------------------------
__global__ void entropy_kernel(const float* __restrict__ logits) {
    __shared__ float sp[NC_SZ];
    int tid = threadIdx.x;
    for (int c = tid; c < NC_SZ; c += blockDim.x) sp[c] = 0.f;
    __syncthreads();

    int warp = tid >> 5, lane = tid & 31;
    int row = blockIdx.x * 8 + warp;
    const float* lrow = logits + (size_t)row * NC_SZ;

    float v[7];
    int cnt = 0;
    float m = -1e30f;
    for (int c = lane; c < NC_SZ; c += 32) {
        float x = lrow[c];
        v[cnt++] = x;
        m = fmaxf(m, x);
    }
#pragma unroll
    for (int o = 16; o > 0; o >>= 1)
        m = fmaxf(m, __shfl_xor_sync(0xffffffffu, m, o));
    float s = 0.f;
    for (int i = 0; i < cnt; i++) { v[i] = __expf(v[i] - m); s += v[i]; }
#pragma unroll
    for (int o = 16; o > 0; o >>= 1)
        s += __shfl_xor_sync(0xffffffffu, s, o);
    float inv = 1.f / s;
    int k = 0;
    for (int c = lane; c < NC_SZ; c += 32)
        atomicAdd(&sp[c], v[k++] * inv);
    __syncthreads();
    for (int c = tid; c < NC_SZ; c += blockDim.x)
        atomicAdd(&g_meanprobs[c], sp[c]);
}

// ---------------- row L2 normalize (both outputs bf16) --------------------------
__global__ void normalize_kernel(const float* __restrict__ zu,
                                 const float* __restrict__ bf) {
    int row = blockIdx.x;
    const float* src = (blockIdx.y == 0) ? zu : bf;
    __nv_bfloat16* dst = (blockIdx.y == 0) ? g_znorm16 : g_bnorm16;
    const float* srow = src + (size_t)row * D_SZ;
    __nv_bfloat16* drow = dst + (size_t)row * D_SZ;

    float ss = 0.f;
    for (int k = threadIdx.x; k < D_SZ; k += blockDim.x) {
        float x = srow[k];
        ss = fmaf(x, x, ss);
    }
    __shared__ float red[8];
    __shared__ float s_inv;
    int lane = threadIdx.x & 31, w = threadIdx.x >> 5;
#pragma unroll
    for (int o = 16; o > 0; o >>= 1)
        ss += __shfl_xor_sync(0xffffffffu, ss, o);
    if (lane == 0) red[w] = ss;
    __syncthreads();
    if (threadIdx.x == 0) {
        float t = 0.f;
#pragma unroll
        for (int i = 0; i < 8; i++) t += red[i];
        s_inv = 1.f / fmaxf(sqrtf(t), 1e-12f);
    }
    __syncthreads();
    float inv = s_inv;
    for (int k = threadIdx.x; k < D_SZ; k += blockDim.x)
        drow[k] = __float2bfloat16(srow[k] * inv);
}

// ---------------- shared epilogue (f32 acc -> sim/mask/attn/bf16-proj) ----------
#define PITCH 20
#define STG_U32 (2 * 128 * PITCH)        // 5120 u32 = 20480 B per stage
#define NSTAGE 4
#define SMEM_BYTES (NSTAGE * STG_U32 * 4)   // 81920 B
#define TPITCH 132

// mode 0: Cf = acc (f32); mode 1: Cmask = (acc>eps && i!=j), with sym transpose;
// mode 3: Cbf = bf16(acc + bias)
__device__ __forceinline__ void epilogue(
    float* smf, float (*acc)[4][4],
    float* Cf, unsigned char* Cmask, __nv_bfloat16* Cbf, const float* bias,
    int Ntot, int mode, int sym, int rowBase, int colBase,
    int warp_m, int warp_n, int r, int c, int t) {
#pragma unroll
    for (int mt = 0; mt < 4; mt++) {
#pragma unroll
        for (int nt = 0; nt < 4; nt++) {
            const int i0 = rowBase + warp_m + mt * 16 + r;
            const int j0 = colBase + warp_n + nt * 8 + 2 * c;
            const float* a4 = acc[mt][nt];
            if (mode == 0) {
                *(float2*)&Cf[(size_t)i0 * Ntot + j0] = make_float2(a4[0], a4[1]);
                *(float2*)&Cf[(size_t)(i0 + 8) * Ntot + j0] = make_float2(a4[2], a4[3]);
            } else if (mode == 1) {
                unsigned char m0 = (a4[0] > EPSILONF && i0 != j0) ? 1 : 0;
                unsigned char m1 = (a4[1] > EPSILONF && i0 != j0 + 1) ? 1 : 0;
                unsigned char m2 = (a4[2] > EPSILONF && (i0 + 8) != j0) ? 1 : 0;
                unsigned char m3 = (a4[3] > EPSILONF && (i0 + 8) != j0 + 1) ? 1 : 0;
                *(uchar2*)&Cmask[(size_t)i0 * Ntot + j0] = make_uchar2(m0, m1);
                *(uchar2*)&Cmask[(size_t)(i0 + 8) * Ntot + j0] = make_uchar2(m2, m3);
            } else {
                float b0 = __ldg(&bias[j0]), b1 = __ldg(&bias[j0 + 1]);
                *(__nv_bfloat162*)&Cbf[(size_t)i0 * Ntot + j0] =
                    __floats2bfloat162_rn(a4[0] + b0, a4[1] + b1);
                *(__nv_bfloat162*)&Cbf[(size_t)(i0 + 8) * Ntot + j0] =
                    __floats2bfloat162_rn(a4[2] + b0, a4[3] + b1);
            }
        }
    }

    if (sym && rowBase != colBase) {
        __syncthreads();
        if (mode == 0) {
            float* smT = smf;
#pragma unroll
            for (int mt = 0; mt < 4; mt++) {
#pragma unroll
                for (int nt = 0; nt < 4; nt++) {
                    const int li = warp_m + mt * 16 + r;
                    const int lj = warp_n + nt * 8 + 2 * c;
                    const float* a4 = acc[mt][nt];
                    smT[lj * TPITCH + li] = a4[0];
                    smT[(lj + 1) * TPITCH + li] = a4[1];
                    smT[lj * TPITCH + li + 8] = a4[2];
                    smT[(lj + 1) * TPITCH + li + 8] = a4[3];
                }
            }
            __syncthreads();
#pragma unroll
            for (int q = 0; q < 16; q++) {
                int linear = q * 256 + t;
                int lj = linear >> 5;
                int ch = (linear & 31) * 4;
                float4 v = *(float4*)&smT[lj * TPITCH + ch];
                *(float4*)&Cf[(size_t)(colBase + lj) * Ntot + rowBase + ch] = v;
            }
        } else if (mode == 1) {
            unsigned char* smC = (unsigned char*)smf;
#pragma unroll
            for (int mt = 0; mt < 4; mt++) {
#pragma unroll
                for (int nt = 0; nt < 4; nt++) {
                    const int i0 = rowBase + warp_m + mt * 16 + r;
                    const int j0 = colBase + warp_n + nt * 8 + 2 * c;
                    const int li = warp_m + mt * 16 + r;
                    const int lj = warp_n + nt * 8 + 2 * c;
                    const float* a4 = acc[mt][nt];
                    smC[lj * TPITCH + li] = (a4[0] > EPSILONF && i0 != j0) ? 1 : 0;
                    smC[(lj + 1) * TPITCH + li] = (a4[1] > EPSILONF && i0 != j0 + 1) ? 1 : 0;
                    smC[lj * TPITCH + li + 8] = (a4[2] > EPSILONF && (i0 + 8) != j0) ? 1 : 0;
                    smC[(lj + 1) * TPITCH + li + 8] = (a4[3] > EPSILONF && (i0 + 8) != j0 + 1) ? 1 : 0;
                }
            }
            __syncthreads();
#pragma unroll
            for (int q = 0; q < 16; q++) {
                int linear = q * 256 + t;
                int lj = linear >> 5;
                int ch = (linear & 31) * 4;
                uchar4 v = *(uchar4*)&smC[lj * TPITCH + ch];
                *(uchar4*)&Cmask[(size_t)(colBase + lj) * Ntot + rowBase + ch] = v;
            }
        }
    }
}

// ---------------- tf32 GEMM body (projections only) ----------------------------
__device__ __forceinline__ void load_stage_f32(uint32_t sbase,
                                               const float* __restrict__ A,
                                               const float* __restrict__ Bm,
                                               int rowBase, int colBase, int K,
                                               int kt, int t) {
    const int k0 = kt * 16;
#pragma unroll
    for (int h = 0; h < 2; h++) {
        int idx = t + h * 256;
        int row = idx >> 2;
        int kc = (idx & 3) * 4;
        CP_ASYNC16(sbase + (uint32_t)(row * PITCH + kc) * 4,
                   A + (size_t)(rowBase + row) * K + k0 + kc);
    }
#pragma unroll
    for (int h = 0; h < 2; h++) {
        int idx = t + h * 256;
        int row = idx >> 2;
        int kc = (idx & 3) * 4;
        CP_ASYNC16(sbase + (uint32_t)(128 * PITCH + row * PITCH + kc) * 4,
                   Bm + (size_t)(colBase + row) * K + k0 + kc);
    }
}

__device__ __forceinline__ void gemm_body_f32(
    float* smf, const float* __restrict__ A, const float* __restrict__ Bm,
    float* Cf, unsigned char* Cmask, __nv_bfloat16* Cbf, const float* bias,
    int Ntot, int K, int mode, int sym, int rowBase, int colBase) {
    const uint32_t su = smem_u32(smf);
    const int t = threadIdx.x;
    const int wid = t >> 5;
    const int lane = t & 31;
    const int r = lane >> 2;
    const int c = lane & 3;
    const int warp_m = (wid & 1) * 64;
    const int warp_n = (wid >> 1) * 32;
    const int KT = K >> 4;

    float acc[4][4][4];
#pragma unroll
    for (int mt = 0; mt < 4; mt++)
#pragma unroll
        for (int nt = 0; nt < 4; nt++)
#pragma unroll
            for (int q = 0; q < 4; q++) acc[mt][nt][q] = 0.f;

#pragma unroll
    for (int s = 0; s < 3; s++) {
        if (s < KT) {
            load_stage_f32(su + s * STG_U32 * 4, A, Bm, rowBase, colBase, K, s, t);
            CP_COMMIT();
        }
    }

    for (int kt = 0; kt < KT; kt++) {
        const int s = kt & (NSTAGE - 1);
        CP_WAIT2();
        __syncthreads();

        const float* As = smf + s * STG_U32;
        const float* Bs = As + 128 * PITCH;
#pragma unroll
        for (int kg = 0; kg < 2; kg++) {
            const int kA = kg * 8 + c;
            uint32_t af[4][4], bf[4][2];
#pragma unroll
            for (int mt = 0; mt < 4; mt++) {
                int m = warp_m + mt * 16 + r;
                af[mt][0] = __float_as_uint(As[m * PITCH + kA]);
                af[mt][1] = __float_as_uint(As[(m + 8) * PITCH + kA]);
                af[mt][2] = __float_as_uint(As[m * PITCH + kA + 4]);
                af[mt][3] = __float_as_uint(As[(m + 8) * PITCH + kA + 4]);
            }
#pragma unroll
            for (int nt = 0; nt < 4; nt++) {
                int n = warp_n + nt * 8 + r;
                bf[nt][0] = __float_as_uint(Bs[n * PITCH + kA]);
                bf[nt][1] = __float_as_uint(Bs[n * PITCH + kA + 4]);
            }
#pragma unroll
            for (int mt = 0; mt < 4; mt++)
#pragma unroll
                for (int nt = 0; nt < 4; nt++)
                    mma_tf32(acc[mt][nt], af[mt], bf[nt]);
        }
        __syncthreads();

        const int kn = kt + 3;
        if (kn < KT) {
            load_stage_f32(su + (kn & (NSTAGE - 1)) * STG_U32 * 4,
                           A, Bm, rowBase, colBase, K, kn, t);
            CP_COMMIT();
        }
    }

    epilogue(smf, acc, Cf, Cmask, Cbf, bias, Ntot, mode, sym, rowBase, colBase,
             warp_m, warp_n, r, c, t);
}

// ---------------- bf16 GEMM body (K-step 32, m16n8k16) -------------------------
__device__ __forceinline__ void load_stage_bf16(uint32_t sbase,
                                                const __nv_bfloat16* __restrict__ A,
                                                const __nv_bfloat16* __restrict__ Bm,
                                                int rowBase, int colBase, int K,
                                                int kt, int t) {
    const int k0 = kt * 32;
#pragma unroll
    for (int h = 0; h < 2; h++) {
        int idx = t + h * 256;
        int row = idx >> 2;
        int kc = idx & 3;                 // 16B chunk (8 bf16)
        CP_ASYNC16(sbase + (uint32_t)(row * PITCH + kc * 4) * 4,
                   A + (size_t)(rowBase + row) * K + k0 + kc * 8);
    }
#pragma unroll
    for (int h = 0; h < 2; h++) {
        int idx = t + h * 256;
        int row = idx >> 2;
        int kc = idx & 3;
        CP_ASYNC16(sbase + (uint32_t)(128 * PITCH + row * PITCH + kc * 4) * 4,
                   Bm + (size_t)(colBase + row) * K + k0 + kc * 8);
    }
}

__device__ __forceinline__ void gemm_body_bf16(
    float* smf, const __nv_bfloat16* __restrict__ A,
    const __nv_bfloat16* __restrict__ Bm,
    float* Cf, unsigned char* Cmask,
    int Ntot, int K, int mode, int sym, int rowBase, int colBase) {
    const uint32_t su = smem_u32(smf);
    const int t = threadIdx.x;
    const int wid = t >> 5;
    const int lane = t & 31;
    const int r = lane >> 2;
    const int c = lane & 3;
    const int warp_m = (wid & 1) * 64;
    const int warp_n = (wid >> 1) * 32;
    const int KT = K >> 5;                // 32 bf16 per k-step

    float acc[4][4][4];
#pragma unroll
    for (int mt = 0; mt < 4; mt++)
#pragma unroll
        for (int nt = 0; nt < 4; nt++)
#pragma unroll
            for (int q = 0; q < 4; q++) acc[mt][nt][q] = 0.f;

#pragma unroll
    for (int s = 0; s < 3; s++) {
        if (s < KT) {
            load_stage_bf16(su + s * STG_U32 * 4, A, Bm, rowBase, colBase, K, s, t);
            CP_COMMIT();
        }
    }

    for (int kt = 0; kt < KT; kt++) {
        const int s = kt & (NSTAGE - 1);
        CP_WAIT2();
        __syncthreads();

        const uint32_t* As = (const uint32_t*)smf + s * STG_U32;
        const uint32_t* Bs = As + 128 * PITCH;
#pragma unroll
        for (int kg = 0; kg < 2; kg++) {            // two k16 halves of the 32-chunk
            const int o = kg * 8 + c;               // u32 index within 16-u32 row
            uint32_t af[4][4], bfr[4][2];
#pragma unroll
            for (int mt = 0; mt < 4; mt++) {
                int m = warp_m + mt * 16 + r;
                af[mt][0] = As[m * PITCH + o];
                af[mt][1] = As[(m + 8) * PITCH + o];
                af[mt][2] = As[m * PITCH + o + 4];
                af[mt][3] = As[(m + 8) * PITCH + o + 4];
            }
#pragma unroll
            for (int nt = 0; nt < 4; nt++) {
                int n = warp_n + nt * 8 + r;
                bfr[nt][0] = Bs[n * PITCH + o];
                bfr[nt][1] = Bs[n * PITCH + o + 4];
            }
#pragma unroll
            for (int mt = 0; mt < 4; mt++)
#pragma unroll
                for (int nt = 0; nt < 4; nt++)
                    mma_bf16(acc[mt][nt], af[mt], bfr[nt]);
        }
        __syncthreads();

        const int kn = kt + 3;
        if (kn < KT) {
            load_stage_bf16(su + (kn & (NSTAGE - 1)) * STG_U32 * 4,
                            A, Bm, rowBase, colBase, K, kn, t);
            CP_COMMIT();
        }
    }

    epilogue(smf, acc, Cf, Cmask, nullptr, nullptr, Ntot, mode, sym,
             rowBase, colBase, warp_m, warp_n, r, c, t);
}

// ---------------- fused big-GEMM launch: sim + mask + attn (all bf16) ----------
__global__ void __launch_bounds__(256, 2)
fused_gemm(float* __restrict__ sim, unsigned char* __restrict__ maskp,
           float* __restrict__ attn) {
    extern __shared__ float smf[];
    int bid = blockIdx.x;

    if (bid < 2 * SIM_TILES) {
        int tt = (bid >= SIM_TILES) ? bid - SIM_TILES : bid;
        int x = (int)((sqrtf(8.f * tt + 1.f) - 1.f) * 0.5f);
        while ((x + 1) * (x + 2) / 2 <= tt) x++;
        while (x * (x + 1) / 2 > tt) x--;
        int bx = x;
        int by = tt - x * (x + 1) / 2;
        if (bid < SIM_TILES) {
            gemm_body_bf16(smf, g_znorm16, g_znorm16, sim, nullptr,
                           B_SZ, D_SZ, 0, 1, by * 128, bx * 128);
        } else {
            gemm_body_bf16(smf, g_bnorm16, g_bnorm16, nullptr, maskp,
                           B_SZ, D_SZ, 1, 1, by * 128, bx * 128);
        }
    } else {
        int l = bid - 2 * SIM_TILES;
        int bx = l & 31;
        int by = l >> 5;
        gemm_body_bf16(smf, g_f1z16, g_f2z16, attn, nullptr,
                       B_SZ, HID_SZ, 0, 0, by * 128, bx * 128);
    }
}

// ---------------- merged projections (tf32 in, bf16 out) ------------------------
__global__ void __launch_bounds__(256, 2)
proj_gemm(const float* __restrict__ zu,
          const float* __restrict__ f1w, const float* __restrict__ f1b,
          const float* __restrict__ f2w, const float* __restrict__ f2b) {
    extern __shared__ float smf[];
    int which = blockIdx.x >> 1;
    int colBase = (blockIdx.x & 1) * 128;
    const float* W = which ? f2w : f1w;
    const float* bias = which ? f2b : f1b;
    __nv_bfloat16* C = which ? g_f2z16 : g_f1z16;
    gemm_body_f32(smf, zu, W, nullptr, nullptr, C, bias, HID_SZ, D_SZ, 3, 0,
                  blockIdx.y * 128, colBase);
}

// ---------------- per-row loss: one block per row, one pass, vectorized ---------
__global__ void __launch_bounds__(256) row_loss_kernel() {
    const int i = blockIdx.x;
    const int t = threadIdx.x;
    const float4* s4p = (const float4*)(g_sim + (size_t)i * B_SZ);
    const uint4* m16p = (const uint4*)(g_mask + (size_t)i * B_SZ);
    const float* arow = g_attn + (size_t)i * B_SZ;

    float den = 0.f, m = -1e30f, Z = 0.f, T = 0.f, n = 0.f;

    const int j0 = t * 16;
    float sv[16];
    {
        float4 a0 = s4p[t * 4 + 0], a1 = s4p[t * 4 + 1];
        float4 a2 = s4p[t * 4 + 2], a3 = s4p[t * 4 + 3];
        sv[0] = a0.x; sv[1] = a0.y; sv[2] = a0.z; sv[3] = a0.w;
        sv[4] = a1.x; sv[5] = a1.y; sv[6] = a1.z; sv[7] = a1.w;
        sv[8] = a2.x; sv[9] = a2.y; sv[10] = a2.z; sv[11] = a2.w;
        sv[12] = a3.x; sv[13] = a3.y; sv[14] = a3.z; sv[15] = a3.w;
    }
    uint4 mw = m16p[t];

#pragma unroll
    for (int q = 0; q < 16; q++) {
        float e = ((q & 3) == 3) ? exp10s_poly(sv[q]) : __expf(sv[q] * INV_TAU);
        if (j0 + q != i) den += e;
    }

    uint32_t ws[4] = {mw.x, mw.y, mw.z, mw.w};
#pragma unroll
    for (int w4 = 0; w4 < 4; w4++) {
        uint32_t w = ws[w4];
        if (w) {
#pragma unroll
            for (int b = 0; b < 4; b++) {
                if ((w >> (8 * b)) & 0xffu) {
                    int q = w4 * 4 + b;
                    n += 1.0f;
                    float a = arow[j0 + q];
                    if (a > m) {
                        float sc = __expf(m - a);
                        Z *= sc; T *= sc; m = a;
                    }
                    float e = __expf(a - m);
                    Z += e;
                    T += e * sv[q];
                }
            }
        }
    }

    int lane = t & 31, wd = t >> 5;
#pragma unroll
    for (int o = 16; o > 0; o >>= 1) {
        float m2 = __shfl_down_sync(0xffffffffu, m, o);
        float Z2 = __shfl_down_sync(0xffffffffu, Z, o);
        float T2 = __shfl_down_sync(0xffffffffu, T, o);
        float d2 = __shfl_down_sync(0xffffffffu, den, o);
        float n2 = __shfl_down_sync(0xffffffffu, n, o);
        float M = fmaxf(m, m2);
        float s1 = __expf(m - M), s2 = __expf(m2 - M);
        Z = Z * s1 + Z2 * s2;
        T = T * s1 + T2 * s2;
        m = M;
        den += d2;
        n += n2;
    }
    __shared__ float sm_[8], sZ_[8], sT_[8], sd_[8], sn_[8];
    if (lane == 0) { sm_[wd] = m; sZ_[wd] = Z; sT_[wd] = T; sd_[wd] = den; sn_[wd] = n; }
    __syncthreads();
    if (wd == 0) {
        if (lane < 8) { m = sm_[lane]; Z = sZ_[lane]; T = sT_[lane]; den = sd_[lane]; n = sn_[lane]; }
        else { m = -1e30f; Z = 0.f; T = 0.f; den = 0.f; n = 0.f; }
#pragma unroll
        for (int o = 4; o > 0; o >>= 1) {
            float m2 = __shfl_down_sync(0xffffffffu, m, o);
            float Z2 = __shfl_down_sync(0xffffffffu, Z, o);
            float T2 = __shfl_down_sync(0xffffffffu, T, o);
            float d2 = __shfl_down_sync(0xffffffffu, den, o);
            float n2 = __shfl_down_sync(0xffffffffu, n, o);
            float M = fmaxf(m, m2);
            float s1 = __expf(m - M), s2 = __expf(m2 - M);
            Z = Z * s1 + Z2 * s2;
            T = T * s1 + T2 * s2;
            m = M;
            den += d2;
            n += n2;
        }
        if (lane == 0 && n > 0.5f) {
            float loss_i = logf(den + EPSF) - (T / Z) * INV_TAU;
            atomicAdd(&g_losssum, loss_i / n);
            atomicAdd(&g_nvalid, 1.0f);
        }
    }
}

// ---------------- finalize ------------------------------------------------------
__global__ void finalize_kernel(float* out) {
    const double invB = 1.0 / (double)B_SZ;
    double pold = 0.0, pnew = 0.0;
    for (int c = 0; c < NOLD_SZ; c++) pold += (double)g_meanprobs[c] * invB;
    for (int c = NOLD_SZ; c < NC_SZ; c++) pnew += (double)g_meanprobs[c] * invB;
    double loss_inter = pold * log(pold + 1e-8) + pnew * log(pnew + 1e-8) + log(2.0);
    double lo = 0.0;
    for (int c = 0; c < NOLD_SZ; c++) {
        double q = ((double)g_meanprobs[c] * invB) / (pold + 1e-8);
        lo += q * log(q + 1e-8);
    }
    lo += log((double)NOLD_SZ);
    double ln_ = 0.0;
    for (int c = NOLD_SZ; c < NC_SZ; c++) {
        double q = ((double)g_meanprobs[c] * invB) / (pnew + 1e-8);
        ln_ += q * log(q + 1e-8);
    }
    ln_ += log((double)NNEW_SZ);
    double le = loss_inter + lo + ln_;

    float nv = g_nvalid;
    float lc = (nv > 0.f) ? (g_losssum / fmaxf(nv, 1.0f)) : 0.f;
    out[0] = (float)le + lc;
}

// ---------------- launch --------------------------------------------------------
extern "C" void kernel_launch(void* const* d_in, const int* in_sizes, int n_in,
                              void* d_out, int out_size) {
    const float* z_u    = (const float*)d_in[0];
    const float* logits = (const float*)d_in[1];
    const float* base   = (const float*)d_in[4];
    const float* f1w    = (const float*)d_in[5];
    const float* f1b    = (const float*)d_in[6];
    const float* f2w    = (const float*)d_in[7];
    const float* f2b    = (const float*)d_in[8];
    float* out = (float*)d_out;
    (void)in_sizes; (void)n_in; (void)out_size;

    void *ps, *pa, *pm;
    cudaGetSymbolAddress(&ps, g_sim);
    cudaGetSymbolAddress(&pa, g_attn);
    cudaGetSymbolAddress(&pm, g_mask);

    cudaFuncSetAttribute(fused_gemm, cudaFuncAttributeMaxDynamicSharedMemorySize, SMEM_BYTES);
    cudaFuncSetAttribute(proj_gemm, cudaFuncAttributeMaxDynamicSharedMemorySize, SMEM_BYTES);

    zero_kernel<<<1, 256>>>();
    entropy_kernel<<<B_SZ / 8, 256>>>(logits);
    normalize_kernel<<<dim3(B_SZ, 2), 256>>>(z_u, base);

    // both projections in one launch (128 CTAs), outputs bf16
    proj_gemm<<<dim3(4, B_SZ / 128), 256, SMEM_BYTES>>>(z_u, f1w, f1b, f2w, f2b);

    // sim + mask + attn, all bf16, one launch (2080 CTAs)
    fused_gemm<<<2 * SIM_TILES + (B_SZ / 128) * (B_SZ / 128), 256, SMEM_BYTES>>>(
        (float*)ps, (unsigned char*)pm, (float*)pa);

    row_loss_kernel<<<B_SZ, 256>>>();
    finalize_kernel<<<1, 1>>>(out);
}

// round 16
// speedup vs baseline: 1.0331x; 1.0331x over previous
#include <cuda_runtime.h>
#include <cuda_bf16.h>
#include <math.h>
#include <stdint.h>

// Problem constants
#define B_SZ    4096
#define D_SZ    768
#define HID_SZ  256
#define NC_SZ   200
#define NOLD_SZ 100
#define NNEW_SZ 100
#define EPSILONF 0.05f
#define INV_TAU  10.0f
#define EPSF     1e-8f
#define SIM_TILES 528            // 32*33/2 upper-tri 128x128 tiles

// ---------------- device scratch (static: no allocations allowed) -------------
__device__ __nv_bfloat16 g_znorm16[B_SZ * D_SZ];
__device__ __nv_bfloat16 g_bnorm16[B_SZ * D_SZ];
__device__ __nv_bfloat16 g_f1z16[B_SZ * HID_SZ];
__device__ __nv_bfloat16 g_f2z16[B_SZ * HID_SZ];
__device__ float g_sim[(size_t)B_SZ * B_SZ];
__device__ float g_attn[(size_t)B_SZ * B_SZ];
__device__ unsigned char g_mask[(size_t)B_SZ * B_SZ];
__device__ float g_meanprobs[NC_SZ];
__device__ float g_losssum;
__device__ float g_nvalid;

// ---------------- helpers -------------------------------------------------------
__device__ __forceinline__ float to_tf32(float x) {
    float y;
    asm("cvt.rna.tf32.f32 %0, %1;" : "=f"(y) : "f"(x));
    return y;
}
#define CP_ASYNC16(dst, src) \
    asm volatile("cp.async.cg.shared.global [%0], [%1], 16;" :: "r"(dst), "l"(src) : "memory")
#define CP_COMMIT() asm volatile("cp.async.commit_group;" ::: "memory")
#define CP_WAIT2()  asm volatile("cp.async.wait_group 2;" ::: "memory")

__device__ __forceinline__ uint32_t smem_u32(const void* p) {
    uint32_t a;
    asm("{ .reg .u64 t; cvta.to.shared.u64 t, %1; cvt.u32.u64 %0, t; }" : "=r"(a) : "l"(p));
    return a;
}
__device__ __forceinline__ void mma_tf32(float* d, const uint32_t* a, const uint32_t* b) {
    asm volatile(
        "mma.sync.aligned.m16n8k8.row.col.f32.tf32.tf32.f32 "
        "{%0,%1,%2,%3}, {%4,%5,%6,%7}, {%8,%9}, {%0,%1,%2,%3};"
        : "+f"(d[0]), "+f"(d[1]), "+f"(d[2]), "+f"(d[3])
        : "r"(a[0]), "r"(a[1]), "r"(a[2]), "r"(a[3]), "r"(b[0]), "r"(b[1]));
}
__device__ __forceinline__ void mma_bf16(float* d, const uint32_t* a, const uint32_t* b) {
    asm volatile(
        "mma.sync.aligned.m16n8k16.row.col.f32.bf16.bf16.f32 "
        "{%0,%1,%2,%3}, {%4,%5,%6,%7}, {%8,%9}, {%0,%1,%2,%3};"
        : "+f"(d[0]), "+f"(d[1]), "+f"(d[2]), "+f"(d[3])
        : "r"(a[0]), "r"(a[1]), "r"(a[2]), "r"(a[3]), "r"(b[0]), "r"(b[1]));
}

// exp(10*s) on the FMA/ALU pipes (no MUFU)
__device__ __forceinline__ float exp10s_poly(float s) {
    float x = s * 14.426950408889634f;
    float kf = rintf(x);
    float l = (x - kf) * 0.6931471805599453f;
    float p = fmaf(l, 1.0f / 120.0f, 1.0f / 24.0f);
    p = fmaf(p, l, 1.0f / 6.0f);
    p = fmaf(p, l, 0.5f);
    p = fmaf(p, l, 1.0f);
    p = fmaf(p, l, 1.0f);
    int ik = (int)kf;
    return __int_as_float(__float_as_int(p) + (ik << 23));
}

// ---------------- init ---------------------------------------------------------
__global__ void zero_kernel() {
    int t = threadIdx.x;
    if (t < NC_SZ) g_meanprobs[t] = 0.f;
    if (t == 0) { g_losssum = 0.f; g_nvalid = 0.f; }
}

// ---------------- entropy stats -------------------------------------------------
__global__ void entropy_kernel(const float* __restrict__ logits) {
    __shared__ float sp[NC_SZ];
    int tid = threadIdx.x;
    for (int c = tid; c < NC_SZ; c += blockDim.x) sp[c] = 0.f;
    __syncthreads();

    int warp = tid >> 5, lane = tid & 31;
    int row = blockIdx.x * 8 + warp;
    const float* lrow = logits + (size_t)row * NC_SZ;

    float v[7];
    int cnt = 0;
    float m = -1e30f;
    for (int c = lane; c < NC_SZ; c += 32) {
        float x = lrow[c];
        v[cnt++] = x;
        m = fmaxf(m, x);
    }
#pragma unroll
    for (int o = 16; o > 0; o >>= 1)
        m = fmaxf(m, __shfl_xor_sync(0xffffffffu, m, o));
    float s = 0.f;
    for (int i = 0; i < cnt; i++) { v[i] = __expf(v[i] - m); s += v[i]; }
#pragma unroll
    for (int o = 16; o > 0; o >>= 1)
        s += __shfl_xor_sync(0xffffffffu, s, o);
    float inv = 1.f / s;
    int k = 0;
    for (int c = lane; c < NC_SZ; c += 32)
        atomicAdd(&sp[c], v[k++] * inv);
    __syncthreads();
    for (int c = tid; c < NC_SZ; c += blockDim.x)
        atomicAdd(&g_meanprobs[c], sp[c]);
}

// ---------------- row L2 normalize (both outputs bf16) --------------------------
__global__ void normalize_kernel(const float* __restrict__ zu,
                                 const float* __restrict__ bf) {
    int row = blockIdx.x;
    const float* src = (blockIdx.y == 0) ? zu : bf;
    __nv_bfloat16* dst = (blockIdx.y == 0) ? g_znorm16 : g_bnorm16;
    const float* srow = src + (size_t)row * D_SZ;
    __nv_bfloat16* drow = dst + (size_t)row * D_SZ;

    float ss = 0.f;
    for (int k = threadIdx.x; k < D_SZ; k += blockDim.x) {
        float x = srow[k];
        ss = fmaf(x, x, ss);
    }
    __shared__ float red[8];
    __shared__ float s_inv;
    int lane = threadIdx.x & 31, w = threadIdx.x >> 5;
#pragma unroll
    for (int o = 16; o > 0; o >>= 1)
        ss += __shfl_xor_sync(0xffffffffu, ss, o);
    if (lane == 0) red[w] = ss;
    __syncthreads();
    if (threadIdx.x == 0) {
        float t = 0.f;
#pragma unroll
        for (int i = 0; i < 8; i++) t += red[i];
        s_inv = 1.f / fmaxf(sqrtf(t), 1e-12f);
    }
    __syncthreads();
    float inv = s_inv;
    for (int k = threadIdx.x; k < D_SZ; k += blockDim.x)
        drow[k] = __float2bfloat16(srow[k] * inv);
}

// ---------------- shared epilogue (f32 acc -> sim/mask/attn/bf16-proj) ----------
#define PITCH 20
#define STG_U32 (2 * 128 * PITCH)        // 5120 u32 = 20480 B per stage
#define NSTAGE 4
#define SMEM_BYTES (NSTAGE * STG_U32 * 4)   // 81920 B
#define TPITCH 132

// mode 0: Cf = acc (f32); mode 1: Cmask = (acc>eps && i!=j), with sym transpose;
// mode 3: Cbf = bf16(acc + bias)
__device__ __forceinline__ void epilogue(
    float* smf, float (*acc)[4][4],
    float* Cf, unsigned char* Cmask, __nv_bfloat16* Cbf, const float* bias,
    int Ntot, int mode, int sym, int rowBase, int colBase,
    int warp_m, int warp_n, int r, int c, int t) {
#pragma unroll
    for (int mt = 0; mt < 4; mt++) {
#pragma unroll
        for (int nt = 0; nt < 4; nt++) {
            const int i0 = rowBase + warp_m + mt * 16 + r;
            const int j0 = colBase + warp_n + nt * 8 + 2 * c;
            const float* a4 = acc[mt][nt];
            if (mode == 0) {
                *(float2*)&Cf[(size_t)i0 * Ntot + j0] = make_float2(a4[0], a4[1]);
                *(float2*)&Cf[(size_t)(i0 + 8) * Ntot + j0] = make_float2(a4[2], a4[3]);
            } else if (mode == 1) {
                unsigned char m0 = (a4[0] > EPSILONF && i0 != j0) ? 1 : 0;
                unsigned char m1 = (a4[1] > EPSILONF && i0 != j0 + 1) ? 1 : 0;
                unsigned char m2 = (a4[2] > EPSILONF && (i0 + 8) != j0) ? 1 : 0;
                unsigned char m3 = (a4[3] > EPSILONF && (i0 + 8) != j0 + 1) ? 1 : 0;
                *(uchar2*)&Cmask[(size_t)i0 * Ntot + j0] = make_uchar2(m0, m1);
                *(uchar2*)&Cmask[(size_t)(i0 + 8) * Ntot + j0] = make_uchar2(m2, m3);
            } else {
                float b0 = __ldg(&bias[j0]), b1 = __ldg(&bias[j0 + 1]);
                *(__nv_bfloat162*)&Cbf[(size_t)i0 * Ntot + j0] =
                    __floats2bfloat162_rn(a4[0] + b0, a4[1] + b1);
                *(__nv_bfloat162*)&Cbf[(size_t)(i0 + 8) * Ntot + j0] =
                    __floats2bfloat162_rn(a4[2] + b0, a4[3] + b1);
            }
        }
    }

    if (sym && rowBase != colBase) {
        __syncthreads();
        if (mode == 0) {
            float* smT = smf;
#pragma unroll
            for (int mt = 0; mt < 4; mt++) {
#pragma unroll
                for (int nt = 0; nt < 4; nt++) {
                    const int li = warp_m + mt * 16 + r;
                    const int lj = warp_n + nt * 8 + 2 * c;
                    const float* a4 = acc[mt][nt];
                    smT[lj * TPITCH + li] = a4[0];
                    smT[(lj + 1) * TPITCH + li] = a4[1];
                    smT[lj * TPITCH + li + 8] = a4[2];
                    smT[(lj + 1) * TPITCH + li + 8] = a4[3];
                }
            }
            __syncthreads();
#pragma unroll
            for (int q = 0; q < 16; q++) {
                int linear = q * 256 + t;
                int lj = linear >> 5;
                int ch = (linear & 31) * 4;
                float4 v = *(float4*)&smT[lj * TPITCH + ch];
                *(float4*)&Cf[(size_t)(colBase + lj) * Ntot + rowBase + ch] = v;
            }
        } else if (mode == 1) {
            unsigned char* smC = (unsigned char*)smf;
#pragma unroll
            for (int mt = 0; mt < 4; mt++) {
#pragma unroll
                for (int nt = 0; nt < 4; nt++) {
                    const int i0 = rowBase + warp_m + mt * 16 + r;
                    const int j0 = colBase + warp_n + nt * 8 + 2 * c;
                    const int li = warp_m + mt * 16 + r;
                    const int lj = warp_n + nt * 8 + 2 * c;
                    const float* a4 = acc[mt][nt];
                    smC[lj * TPITCH + li] = (a4[0] > EPSILONF && i0 != j0) ? 1 : 0;
                    smC[(lj + 1) * TPITCH + li] = (a4[1] > EPSILONF && i0 != j0 + 1) ? 1 : 0;
                    smC[lj * TPITCH + li + 8] = (a4[2] > EPSILONF && (i0 + 8) != j0) ? 1 : 0;
                    smC[(lj + 1) * TPITCH + li + 8] = (a4[3] > EPSILONF && (i0 + 8) != j0 + 1) ? 1 : 0;
                }
            }
            __syncthreads();
#pragma unroll
            for (int q = 0; q < 16; q++) {
                int linear = q * 256 + t;
                int lj = linear >> 5;
                int ch = (linear & 31) * 4;
                uchar4 v = *(uchar4*)&smC[lj * TPITCH + ch];
                *(uchar4*)&Cmask[(size_t)(colBase + lj) * Ntot + rowBase + ch] = v;
            }
        }
    }
}

// ---------------- tf32 GEMM body (projections only) ----------------------------
__device__ __forceinline__ void load_stage_f32(uint32_t sbase,
                                               const float* __restrict__ A,
                                               const float* __restrict__ Bm,
                                               int rowBase, int colBase, int K,
                                               int kt, int t) {
    const int k0 = kt * 16;
#pragma unroll
    for (int h = 0; h < 2; h++) {
        int idx = t + h * 256;
        int row = idx >> 2;
        int kc = (idx & 3) * 4;
        CP_ASYNC16(sbase + (uint32_t)(row * PITCH + kc) * 4,
                   A + (size_t)(rowBase + row) * K + k0 + kc);
    }
#pragma unroll
    for (int h = 0; h < 2; h++) {
        int idx = t + h * 256;
        int row = idx >> 2;
        int kc = (idx & 3) * 4;
        CP_ASYNC16(sbase + (uint32_t)(128 * PITCH + row * PITCH + kc) * 4,
                   Bm + (size_t)(colBase + row) * K + k0 + kc);
    }
}

__device__ __forceinline__ void gemm_body_f32(
    float* smf, const float* __restrict__ A, const float* __restrict__ Bm,
    float* Cf, unsigned char* Cmask, __nv_bfloat16* Cbf, const float* bias,
    int Ntot, int K, int mode, int sym, int rowBase, int colBase) {
    const uint32_t su = smem_u32(smf);
    const int t = threadIdx.x;
    const int wid = t >> 5;
    const int lane = t & 31;
    const int r = lane >> 2;
    const int c = lane & 3;
    const int warp_m = (wid & 1) * 64;
    const int warp_n = (wid >> 1) * 32;
    const int KT = K >> 4;

    float acc[4][4][4];
#pragma unroll
    for (int mt = 0; mt < 4; mt++)
#pragma unroll
        for (int nt = 0; nt < 4; nt++)
#pragma unroll
            for (int q = 0; q < 4; q++) acc[mt][nt][q] = 0.f;

#pragma unroll
    for (int s = 0; s < 3; s++) {
        if (s < KT) {
            load_stage_f32(su + s * STG_U32 * 4, A, Bm, rowBase, colBase, K, s, t);
            CP_COMMIT();
        }
    }

    for (int kt = 0; kt < KT; kt++) {
        const int s = kt & (NSTAGE - 1);
        CP_WAIT2();
        __syncthreads();

        const float* As = smf + s * STG_U32;
        const float* Bs = As + 128 * PITCH;
#pragma unroll
        for (int kg = 0; kg < 2; kg++) {
            const int kA = kg * 8 + c;
            uint32_t af[4][4], bf[4][2];
#pragma unroll
            for (int mt = 0; mt < 4; mt++) {
                int m = warp_m + mt * 16 + r;
                af[mt][0] = __float_as_uint(As[m * PITCH + kA]);
                af[mt][1] = __float_as_uint(As[(m + 8) * PITCH + kA]);
                af[mt][2] = __float_as_uint(As[m * PITCH + kA + 4]);
                af[mt][3] = __float_as_uint(As[(m + 8) * PITCH + kA + 4]);
            }
#pragma unroll
            for (int nt = 0; nt < 4; nt++) {
                int n = warp_n + nt * 8 + r;
                bf[nt][0] = __float_as_uint(Bs[n * PITCH + kA]);
                bf[nt][1] = __float_as_uint(Bs[n * PITCH + kA + 4]);
            }
#pragma unroll
            for (int mt = 0; mt < 4; mt++)
#pragma unroll
                for (int nt = 0; nt < 4; nt++)
                    mma_tf32(acc[mt][nt], af[mt], bf[nt]);
        }
        __syncthreads();

        const int kn = kt + 3;
        if (kn < KT) {
            load_stage_f32(su + (kn & (NSTAGE - 1)) * STG_U32 * 4,
                           A, Bm, rowBase, colBase, K, kn, t);
            CP_COMMIT();
        }
    }

    epilogue(smf, acc, Cf, Cmask, Cbf, bias, Ntot, mode, sym, rowBase, colBase,
             warp_m, warp_n, r, c, t);
}

// ---------------- bf16 GEMM body (K-step 32, m16n8k16) -------------------------
__device__ __forceinline__ void load_stage_bf16(uint32_t sbase,
                                                const __nv_bfloat16* __restrict__ A,
                                                const __nv_bfloat16* __restrict__ Bm,
                                                int rowBase, int colBase, int K,
                                                int kt, int t) {
    const int k0 = kt * 32;
#pragma unroll
    for (int h = 0; h < 2; h++) {
        int idx = t + h * 256;
        int row = idx >> 2;
        int kc = idx & 3;                 // 16B chunk (8 bf16)
        CP_ASYNC16(sbase + (uint32_t)(row * PITCH + kc * 4) * 4,
                   A + (size_t)(rowBase + row) * K + k0 + kc * 8);
    }
#pragma unroll
    for (int h = 0; h < 2; h++) {
        int idx = t + h * 256;
        int row = idx >> 2;
        int kc = idx & 3;
        CP_ASYNC16(sbase + (uint32_t)(128 * PITCH + row * PITCH + kc * 4) * 4,
                   Bm + (size_t)(colBase + row) * K + k0 + kc * 8);
    }
}

__device__ __forceinline__ void gemm_body_bf16(
    float* smf, const __nv_bfloat16* __restrict__ A,
    const __nv_bfloat16* __restrict__ Bm,
    float* Cf, unsigned char* Cmask,
    int Ntot, int K, int mode, int sym, int rowBase, int colBase) {
    const uint32_t su = smem_u32(smf);
    const int t = threadIdx.x;
    const int wid = t >> 5;
    const int lane = t & 31;
    const int r = lane >> 2;
    const int c = lane & 3;
    const int warp_m = (wid & 1) * 64;
    const int warp_n = (wid >> 1) * 32;
    const int KT = K >> 5;                // 32 bf16 per k-step

    float acc[4][4][4];
#pragma unroll
    for (int mt = 0; mt < 4; mt++)
#pragma unroll
        for (int nt = 0; nt < 4; nt++)
#pragma unroll
            for (int q = 0; q < 4; q++) acc[mt][nt][q] = 0.f;

#pragma unroll
    for (int s = 0; s < 3; s++) {
        if (s < KT) {
            load_stage_bf16(su + s * STG_U32 * 4, A, Bm, rowBase, colBase, K, s, t);
            CP_COMMIT();
        }
    }

    for (int kt = 0; kt < KT; kt++) {
        const int s = kt & (NSTAGE - 1);
        CP_WAIT2();
        __syncthreads();

        const uint32_t* As = (const uint32_t*)smf + s * STG_U32;
        const uint32_t* Bs = As + 128 * PITCH;
#pragma unroll
        for (int kg = 0; kg < 2; kg++) {            // two k16 halves of the 32-chunk
            const int o = kg * 8 + c;               // u32 index within 16-u32 row
            uint32_t af[4][4], bfr[4][2];
#pragma unroll
            for (int mt = 0; mt < 4; mt++) {
                int m = warp_m + mt * 16 + r;
                af[mt][0] = As[m * PITCH + o];
                af[mt][1] = As[(m + 8) * PITCH + o];
                af[mt][2] = As[m * PITCH + o + 4];
                af[mt][3] = As[(m + 8) * PITCH + o + 4];
            }
#pragma unroll
            for (int nt = 0; nt < 4; nt++) {
                int n = warp_n + nt * 8 + r;
                bfr[nt][0] = Bs[n * PITCH + o];
                bfr[nt][1] = Bs[n * PITCH + o + 4];
            }
#pragma unroll
            for (int mt = 0; mt < 4; mt++)
#pragma unroll
                for (int nt = 0; nt < 4; nt++)
                    mma_bf16(acc[mt][nt], af[mt], bfr[nt]);
        }
        __syncthreads();

        const int kn = kt + 3;
        if (kn < KT) {
            load_stage_bf16(su + (kn & (NSTAGE - 1)) * STG_U32 * 4,
                            A, Bm, rowBase, colBase, K, kn, t);
            CP_COMMIT();
        }
    }

    epilogue(smf, acc, Cf, Cmask, nullptr, nullptr, Ntot, mode, sym,
             rowBase, colBase, warp_m, warp_n, r, c, t);
}

// ---------------- fused big-GEMM launch: sim + mask + attn (all bf16) ----------
__global__ void __launch_bounds__(256, 2)
fused_gemm(float* __restrict__ sim, unsigned char* __restrict__ maskp,
           float* __restrict__ attn) {
    extern __shared__ float smf[];
    int bid = blockIdx.x;

    if (bid < 2 * SIM_TILES) {
        int tt = (bid >= SIM_TILES) ? bid - SIM_TILES : bid;
        int x = (int)((sqrtf(8.f * tt + 1.f) - 1.f) * 0.5f);
        while ((x + 1) * (x + 2) / 2 <= tt) x++;
        while (x * (x + 1) / 2 > tt) x--;
        int bx = x;
        int by = tt - x * (x + 1) / 2;
        if (bid < SIM_TILES) {
            gemm_body_bf16(smf, g_znorm16, g_znorm16, sim, nullptr,
                           B_SZ, D_SZ, 0, 1, by * 128, bx * 128);
        } else {
            gemm_body_bf16(smf, g_bnorm16, g_bnorm16, nullptr, maskp,
                           B_SZ, D_SZ, 1, 1, by * 128, bx * 128);
        }
    } else {
        int l = bid - 2 * SIM_TILES;
        int bx = l & 31;
        int by = l >> 5;
        gemm_body_bf16(smf, g_f1z16, g_f2z16, attn, nullptr,
                       B_SZ, HID_SZ, 0, 0, by * 128, bx * 128);
    }
}

// ---------------- merged projections (tf32 in, bf16 out) ------------------------
__global__ void __launch_bounds__(256, 2)
proj_gemm(const float* __restrict__ zu,
          const float* __restrict__ f1w, const float* __restrict__ f1b,
          const float* __restrict__ f2w, const float* __restrict__ f2b) {
    extern __shared__ float smf[];
    int which = blockIdx.x >> 1;
    int colBase = (blockIdx.x & 1) * 128;
    const float* W = which ? f2w : f1w;
    const float* bias = which ? f2b : f1b;
    __nv_bfloat16* C = which ? g_f2z16 : g_f1z16;
    gemm_body_f32(smf, zu, W, nullptr, nullptr, C, bias, HID_SZ, D_SZ, 3, 0,
                  blockIdx.y * 128, colBase);
}

// ---------------- per-row loss: one block per row, one pass, vectorized ---------
__global__ void __launch_bounds__(256) row_loss_kernel() {
    const int i = blockIdx.x;
    const int t = threadIdx.x;
    const float4* s4p = (const float4*)(g_sim + (size_t)i * B_SZ);
    const uint4* m16p = (const uint4*)(g_mask + (size_t)i * B_SZ);
    const float* arow = g_attn + (size_t)i * B_SZ;

    float den = 0.f, m = -1e30f, Z = 0.f, T = 0.f, n = 0.f;

    const int j0 = t * 16;
    float sv[16];
    {
        float4 a0 = s4p[t * 4 + 0], a1 = s4p[t * 4 + 1];
        float4 a2 = s4p[t * 4 + 2], a3 = s4p[t * 4 + 3];
        sv[0] = a0.x; sv[1] = a0.y; sv[2] = a0.z; sv[3] = a0.w;
        sv[4] = a1.x; sv[5] = a1.y; sv[6] = a1.z; sv[7] = a1.w;
        sv[8] = a2.x; sv[9] = a2.y; sv[10] = a2.z; sv[11] = a2.w;
        sv[12] = a3.x; sv[13] = a3.y; sv[14] = a3.z; sv[15] = a3.w;
    }
    uint4 mw = m16p[t];

#pragma unroll
    for (int q = 0; q < 16; q++) {
        float e = ((q & 3) == 3) ? exp10s_poly(sv[q]) : __expf(sv[q] * INV_TAU);
        if (j0 + q != i) den += e;
    }

    uint32_t ws[4] = {mw.x, mw.y, mw.z, mw.w};
#pragma unroll
    for (int w4 = 0; w4 < 4; w4++) {
        uint32_t w = ws[w4];
        if (w) {
#pragma unroll
            for (int b = 0; b < 4; b++) {
                if ((w >> (8 * b)) & 0xffu) {
                    int q = w4 * 4 + b;
                    n += 1.0f;
                    float a = arow[j0 + q];
                    if (a > m) {
                        float sc = __expf(m - a);
                        Z *= sc; T *= sc; m = a;
                    }
                    float e = __expf(a - m);
                    Z += e;
                    T += e * sv[q];
                }
            }
        }
    }

    int lane = t & 31, wd = t >> 5;
#pragma unroll
    for (int o = 16; o > 0; o >>= 1) {
        float m2 = __shfl_down_sync(0xffffffffu, m, o);
        float Z2 = __shfl_down_sync(0xffffffffu, Z, o);
        float T2 = __shfl_down_sync(0xffffffffu, T, o);
        float d2 = __shfl_down_sync(0xffffffffu, den, o);
        float n2 = __shfl_down_sync(0xffffffffu, n, o);
        float M = fmaxf(m, m2);
        float s1 = __expf(m - M), s2 = __expf(m2 - M);
        Z = Z * s1 + Z2 * s2;
        T = T * s1 + T2 * s2;
        m = M;
        den += d2;
        n += n2;
    }
    __shared__ float sm_[8], sZ_[8], sT_[8], sd_[8], sn_[8];
    if (lane == 0) { sm_[wd] = m; sZ_[wd] = Z; sT_[wd] = T; sd_[wd] = den; sn_[wd] = n; }
    __syncthreads();
    if (wd == 0) {
        if (lane < 8) { m = sm_[lane]; Z = sZ_[lane]; T = sT_[lane]; den = sd_[lane]; n = sn_[lane]; }
        else { m = -1e30f; Z = 0.f; T = 0.f; den = 0.f; n = 0.f; }
#pragma unroll
        for (int o = 4; o > 0; o >>= 1) {
            float m2 = __shfl_down_sync(0xffffffffu, m, o);
            float Z2 = __shfl_down_sync(0xffffffffu, Z, o);
            float T2 = __shfl_down_sync(0xffffffffu, T, o);
            float d2 = __shfl_down_sync(0xffffffffu, den, o);
            float n2 = __shfl_down_sync(0xffffffffu, n, o);
            float M = fmaxf(m, m2);
            float s1 = __expf(m - M), s2 = __expf(m2 - M);
            Z = Z * s1 + Z2 * s2;
            T = T * s1 + T2 * s2;
            m = M;
            den += d2;
            n += n2;
        }
        if (lane == 0 && n > 0.5f) {
            float loss_i = logf(den + EPSF) - (T / Z) * INV_TAU;
            atomicAdd(&g_losssum, loss_i / n);
            atomicAdd(&g_nvalid, 1.0f);
        }
    }
}

// ---------------- finalize ------------------------------------------------------
__global__ void finalize_kernel(float* out) {
    const double invB = 1.0 / (double)B_SZ;
    double pold = 0.0, pnew = 0.0;
    for (int c = 0; c < NOLD_SZ; c++) pold += (double)g_meanprobs[c] * invB;
    for (int c = NOLD_SZ; c < NC_SZ; c++) pnew += (double)g_meanprobs[c] * invB;
    double loss_inter = pold * log(pold + 1e-8) + pnew * log(pnew + 1e-8) + log(2.0);
    double lo = 0.0;
    for (int c = 0; c < NOLD_SZ; c++) {
        double q = ((double)g_meanprobs[c] * invB) / (pold + 1e-8);
        lo += q * log(q + 1e-8);
    }
    lo += log((double)NOLD_SZ);
    double ln_ = 0.0;
    for (int c = NOLD_SZ; c < NC_SZ; c++) {
        double q = ((double)g_meanprobs[c] * invB) / (pnew + 1e-8);
        ln_ += q * log(q + 1e-8);
    }
    ln_ += log((double)NNEW_SZ);
    double le = loss_inter + lo + ln_;

    float nv = g_nvalid;
    float lc = (nv > 0.f) ? (g_losssum / fmaxf(nv, 1.0f)) : 0.f;
    out[0] = (float)le + lc;
}

// ---------------- launch --------------------------------------------------------
extern "C" void kernel_launch(void* const* d_in, const int* in_sizes, int n_in,
                              void* d_out, int out_size) {
    const float* z_u    = (const float*)d_in[0];
    const float* logits = (const float*)d_in[1];
    const float* base   = (const float*)d_in[4];
    const float* f1w    = (const float*)d_in[5];
    const float* f1b    = (const float*)d_in[6];
    const float* f2w    = (const float*)d_in[7];
    const float* f2b    = (const float*)d_in[8];
    float* out = (float*)d_out;
    (void)in_sizes; (void)n_in; (void)out_size;

    void *ps, *pa, *pm;
    cudaGetSymbolAddress(&ps, g_sim);
    cudaGetSymbolAddress(&pa, g_attn);
    cudaGetSymbolAddress(&pm, g_mask);

    cudaFuncSetAttribute(fused_gemm, cudaFuncAttributeMaxDynamicSharedMemorySize, SMEM_BYTES);
    cudaFuncSetAttribute(proj_gemm, cudaFuncAttributeMaxDynamicSharedMemorySize, SMEM_BYTES);

    zero_kernel<<<1, 256>>>();
    entropy_kernel<<<B_SZ / 8, 256>>>(logits);
    normalize_kernel<<<dim3(B_SZ, 2), 256>>>(z_u, base);

    // both projections in one launch (128 CTAs), outputs bf16
    proj_gemm<<<dim3(4, B_SZ / 128), 256, SMEM_BYTES>>>(z_u, f1w, f1b, f2w, f2b);

    // sim + mask + attn, all bf16, one launch (2080 CTAs)
    fused_gemm<<<2 * SIM_TILES + (B_SZ / 128) * (B_SZ / 128), 256, SMEM_BYTES>>>(
        (float*)ps, (unsigned char*)pm, (float*)pa);

    row_loss_kernel<<<B_SZ, 256>>>();
    finalize_kernel<<<1, 1>>>(out);
}

// round 17
// speedup vs baseline: 1.0370x; 1.0037x over previous
#include <cuda_runtime.h>
#include <cuda_bf16.h>
#include <math.h>
#include <stdint.h>

// Problem constants
#define B_SZ    4096
#define D_SZ    768
#define HID_SZ  256
#define NC_SZ   200
#define NOLD_SZ 100
#define NNEW_SZ 100
#define EPSILONF 0.05f
#define INV_TAU  10.0f
#define EPSF     1e-8f
#define SIM_TILES 528            // 32*33/2 upper-tri 128x128 tiles

// ---------------- device scratch (static: no allocations allowed) -------------
__device__ __nv_bfloat16 g_znorm16[B_SZ * D_SZ];
__device__ __nv_bfloat16 g_bnorm16[B_SZ * D_SZ];
__device__ __nv_bfloat16 g_f1z16[B_SZ * HID_SZ];
__device__ __nv_bfloat16 g_f2z16[B_SZ * HID_SZ];
__device__ float g_sim[(size_t)B_SZ * B_SZ];
__device__ float g_attn[(size_t)B_SZ * B_SZ];
__device__ unsigned char g_mask[(size_t)B_SZ * B_SZ];
__device__ float g_meanprobs[NC_SZ];
__device__ float g_losssum;
__device__ float g_nvalid;

// ---------------- helpers -------------------------------------------------------
__device__ __forceinline__ float to_tf32(float x) {
    float y;
    asm("cvt.rna.tf32.f32 %0, %1;" : "=f"(y) : "f"(x));
    return y;
}
#define CP_ASYNC16(dst, src) \
    asm volatile("cp.async.cg.shared.global [%0], [%1], 16;" :: "r"(dst), "l"(src) : "memory")
#define CP_COMMIT() asm volatile("cp.async.commit_group;" ::: "memory")
#define CP_WAIT2()  asm volatile("cp.async.wait_group 2;" ::: "memory")

__device__ __forceinline__ uint32_t smem_u32(const void* p) {
    uint32_t a;
    asm("{ .reg .u64 t; cvta.to.shared.u64 t, %1; cvt.u32.u64 %0, t; }" : "=r"(a) : "l"(p));
    return a;
}
__device__ __forceinline__ void mma_tf32(float* d, const uint32_t* a, const uint32_t* b) {
    asm volatile(
        "mma.sync.aligned.m16n8k8.row.col.f32.tf32.tf32.f32 "
        "{%0,%1,%2,%3}, {%4,%5,%6,%7}, {%8,%9}, {%0,%1,%2,%3};"
        : "+f"(d[0]), "+f"(d[1]), "+f"(d[2]), "+f"(d[3])
        : "r"(a[0]), "r"(a[1]), "r"(a[2]), "r"(a[3]), "r"(b[0]), "r"(b[1]));
}
__device__ __forceinline__ void mma_bf16(float* d, const uint32_t* a, const uint32_t* b) {
    asm volatile(
        "mma.sync.aligned.m16n8k16.row.col.f32.bf16.bf16.f32 "
        "{%0,%1,%2,%3}, {%4,%5,%6,%7}, {%8,%9}, {%0,%1,%2,%3};"
        : "+f"(d[0]), "+f"(d[1]), "+f"(d[2]), "+f"(d[3])
        : "r"(a[0]), "r"(a[1]), "r"(a[2]), "r"(a[3]), "r"(b[0]), "r"(b[1]));
}

// exp(10*s) on the FMA/ALU pipes (no MUFU)
__device__ __forceinline__ float exp10s_poly(float s) {
    float x = s * 14.426950408889634f;
    float kf = rintf(x);
    float l = (x - kf) * 0.6931471805599453f;
    float p = fmaf(l, 1.0f / 120.0f, 1.0f / 24.0f);
    p = fmaf(p, l, 1.0f / 6.0f);
    p = fmaf(p, l, 0.5f);
    p = fmaf(p, l, 1.0f);
    p = fmaf(p, l, 1.0f);
    int ik = (int)kf;
    return __int_as_float(__float_as_int(p) + (ik << 23));
}

// ---------------- init ---------------------------------------------------------
__global__ void zero_kernel() {
    int t = threadIdx.x;
    if (t < NC_SZ) g_meanprobs[t] = 0.f;
    if (t == 0) { g_losssum = 0.f; g_nvalid = 0.f; }
}

// ---------------- entropy stats -------------------------------------------------
__global__ void entropy_kernel(const float* __restrict__ logits) {
    __shared__ float sp[NC_SZ];
    int tid = threadIdx.x;
    for (int c = tid; c < NC_SZ; c += blockDim.x) sp[c] = 0.f;
    __syncthreads();

    int warp = tid >> 5, lane = tid & 31;
    int row = blockIdx.x * 8 + warp;
    const float* lrow = logits + (size_t)row * NC_SZ;

    float v[7];
    int cnt = 0;
    float m = -1e30f;
    for (int c = lane; c < NC_SZ; c += 32) {
        float x = lrow[c];
        v[cnt++] = x;
        m = fmaxf(m, x);
    }
#pragma unroll
    for (int o = 16; o > 0; o >>= 1)
        m = fmaxf(m, __shfl_xor_sync(0xffffffffu, m, o));
    float s = 0.f;
    for (int i = 0; i < cnt; i++) { v[i] = __expf(v[i] - m); s += v[i]; }
#pragma unroll
    for (int o = 16; o > 0; o >>= 1)
        s += __shfl_xor_sync(0xffffffffu, s, o);
    float inv = 1.f / s;
    int k = 0;
    for (int c = lane; c < NC_SZ; c += 32)
        atomicAdd(&sp[c], v[k++] * inv);
    __syncthreads();
    for (int c = tid; c < NC_SZ; c += blockDim.x)
        atomicAdd(&g_meanprobs[c], sp[c]);
}

// ---------------- row L2 normalize (both outputs bf16) --------------------------
__global__ void normalize_kernel(const float* __restrict__ zu,
                                 const float* __restrict__ bf) {
    int row = blockIdx.x;
    const float* src = (blockIdx.y == 0) ? zu : bf;
    __nv_bfloat16* dst = (blockIdx.y == 0) ? g_znorm16 : g_bnorm16;
    const float* srow = src + (size_t)row * D_SZ;
    __nv_bfloat16* drow = dst + (size_t)row * D_SZ;

    float ss = 0.f;
    for (int k = threadIdx.x; k < D_SZ; k += blockDim.x) {
        float x = srow[k];
        ss = fmaf(x, x, ss);
    }
    __shared__ float red[8];
    __shared__ float s_inv;
    int lane = threadIdx.x & 31, w = threadIdx.x >> 5;
#pragma unroll
    for (int o = 16; o > 0; o >>= 1)
        ss += __shfl_xor_sync(0xffffffffu, ss, o);
    if (lane == 0) red[w] = ss;
    __syncthreads();
    if (threadIdx.x == 0) {
        float t = 0.f;
#pragma unroll
        for (int i = 0; i < 8; i++) t += red[i];
        s_inv = 1.f / fmaxf(sqrtf(t), 1e-12f);
    }
    __syncthreads();
    float inv = s_inv;
    for (int k = threadIdx.x; k < D_SZ; k += blockDim.x)
        drow[k] = __float2bfloat16(srow[k] * inv);
}

// ---------------- shared epilogue (f32 acc -> sim/mask/attn/bf16-proj) ----------
#define PITCH 20
#define STG_U32 (2 * 128 * PITCH)        // 5120 u32 = 20480 B per stage
#define NSTAGE 4
#define SMEM_BYTES (NSTAGE * STG_U32 * 4)   // 81920 B
#define TPITCH 132

// mode 0: Cf = acc (f32); mode 1: Cmask = (acc>eps && i!=j), with sym transpose;
// mode 3: Cbf = bf16(acc + bias)
__device__ __forceinline__ void epilogue(
    float* smf, float (*acc)[4][4],
    float* Cf, unsigned char* Cmask, __nv_bfloat16* Cbf, const float* bias,
    int Ntot, int mode, int sym, int rowBase, int colBase,
    int warp_m, int warp_n, int r, int c, int t) {
#pragma unroll
    for (int mt = 0; mt < 4; mt++) {
#pragma unroll
        for (int nt = 0; nt < 4; nt++) {
            const int i0 = rowBase + warp_m + mt * 16 + r;
            const int j0 = colBase + warp_n + nt * 8 + 2 * c;
            const float* a4 = acc[mt][nt];
            if (mode == 0) {
                *(float2*)&Cf[(size_t)i0 * Ntot + j0] = make_float2(a4[0], a4[1]);
                *(float2*)&Cf[(size_t)(i0 + 8) * Ntot + j0] = make_float2(a4[2], a4[3]);
            } else if (mode == 1) {
                unsigned char m0 = (a4[0] > EPSILONF && i0 != j0) ? 1 : 0;
                unsigned char m1 = (a4[1] > EPSILONF && i0 != j0 + 1) ? 1 : 0;
                unsigned char m2 = (a4[2] > EPSILONF && (i0 + 8) != j0) ? 1 : 0;
                unsigned char m3 = (a4[3] > EPSILONF && (i0 + 8) != j0 + 1) ? 1 : 0;
                *(uchar2*)&Cmask[(size_t)i0 * Ntot + j0] = make_uchar2(m0, m1);
                *(uchar2*)&Cmask[(size_t)(i0 + 8) * Ntot + j0] = make_uchar2(m2, m3);
            } else {
                float b0 = __ldg(&bias[j0]), b1 = __ldg(&bias[j0 + 1]);
                *(__nv_bfloat162*)&Cbf[(size_t)i0 * Ntot + j0] =
                    __floats2bfloat162_rn(a4[0] + b0, a4[1] + b1);
                *(__nv_bfloat162*)&Cbf[(size_t)(i0 + 8) * Ntot + j0] =
                    __floats2bfloat162_rn(a4[2] + b0, a4[3] + b1);
            }
        }
    }

    if (sym && rowBase != colBase) {
        __syncthreads();
        if (mode == 0) {
            float* smT = smf;
#pragma unroll
            for (int mt = 0; mt < 4; mt++) {
#pragma unroll
                for (int nt = 0; nt < 4; nt++) {
                    const int li = warp_m + mt * 16 + r;
                    const int lj = warp_n + nt * 8 + 2 * c;
                    const float* a4 = acc[mt][nt];
                    smT[lj * TPITCH + li] = a4[0];
                    smT[(lj + 1) * TPITCH + li] = a4[1];
                    smT[lj * TPITCH + li + 8] = a4[2];
                    smT[(lj + 1) * TPITCH + li + 8] = a4[3];
                }
            }
            __syncthreads();
#pragma unroll
            for (int q = 0; q < 16; q++) {
                int linear = q * 256 + t;
                int lj = linear >> 5;
                int ch = (linear & 31) * 4;
                float4 v = *(float4*)&smT[lj * TPITCH + ch];
                *(float4*)&Cf[(size_t)(colBase + lj) * Ntot + rowBase + ch] = v;
            }
        } else if (mode == 1) {
            unsigned char* smC = (unsigned char*)smf;
#pragma unroll
            for (int mt = 0; mt < 4; mt++) {
#pragma unroll
                for (int nt = 0; nt < 4; nt++) {
                    const int i0 = rowBase + warp_m + mt * 16 + r;
                    const int j0 = colBase + warp_n + nt * 8 + 2 * c;
                    const int li = warp_m + mt * 16 + r;
                    const int lj = warp_n + nt * 8 + 2 * c;
                    const float* a4 = acc[mt][nt];
                    smC[lj * TPITCH + li] = (a4[0] > EPSILONF && i0 != j0) ? 1 : 0;
                    smC[(lj + 1) * TPITCH + li] = (a4[1] > EPSILONF && i0 != j0 + 1) ? 1 : 0;
                    smC[lj * TPITCH + li + 8] = (a4[2] > EPSILONF && (i0 + 8) != j0) ? 1 : 0;
                    smC[(lj + 1) * TPITCH + li + 8] = (a4[3] > EPSILONF && (i0 + 8) != j0 + 1) ? 1 : 0;
                }
            }
            __syncthreads();
#pragma unroll
            for (int q = 0; q < 16; q++) {
                int linear = q * 256 + t;
                int lj = linear >> 5;
                int ch = (linear & 31) * 4;
                uchar4 v = *(uchar4*)&smC[lj * TPITCH + ch];
                *(uchar4*)&Cmask[(size_t)(colBase + lj) * Ntot + rowBase + ch] = v;
            }
        }
    }
}

// ---------------- tf32 GEMM body (projections only) ----------------------------
__device__ __forceinline__ void load_stage_f32(uint32_t sbase,
                                               const float* __restrict__ A,
                                               const float* __restrict__ Bm,
                                               int rowBase, int colBase, int K,
                                               int kt, int t) {
    const int k0 = kt * 16;
#pragma unroll
    for (int h = 0; h < 2; h++) {
        int idx = t + h * 256;
        int row = idx >> 2;
        int kc = (idx & 3) * 4;
        CP_ASYNC16(sbase + (uint32_t)(row * PITCH + kc) * 4,
                   A + (size_t)(rowBase + row) * K + k0 + kc);
    }
#pragma unroll
    for (int h = 0; h < 2; h++) {
        int idx = t + h * 256;
        int row = idx >> 2;
        int kc = (idx & 3) * 4;
        CP_ASYNC16(sbase + (uint32_t)(128 * PITCH + row * PITCH + kc) * 4,
                   Bm + (size_t)(colBase + row) * K + k0 + kc);
    }
}

__device__ __forceinline__ void gemm_body_f32(
    float* smf, const float* __restrict__ A, const float* __restrict__ Bm,
    float* Cf, unsigned char* Cmask, __nv_bfloat16* Cbf, const float* bias,
    int Ntot, int K, int mode, int sym, int rowBase, int colBase) {
    const uint32_t su = smem_u32(smf);
    const int t = threadIdx.x;
    const int wid = t >> 5;
    const int lane = t & 31;
    const int r = lane >> 2;
    const int c = lane & 3;
    const int warp_m = (wid & 1) * 64;
    const int warp_n = (wid >> 1) * 32;
    const int KT = K >> 4;

    float acc[4][4][4];
#pragma unroll
    for (int mt = 0; mt < 4; mt++)
#pragma unroll
        for (int nt = 0; nt < 4; nt++)
#pragma unroll
            for (int q = 0; q < 4; q++) acc[mt][nt][q] = 0.f;

#pragma unroll
    for (int s = 0; s < 3; s++) {
        if (s < KT) {
            load_stage_f32(su + s * STG_U32 * 4, A, Bm, rowBase, colBase, K, s, t);
            CP_COMMIT();
        }
    }

    for (int kt = 0; kt < KT; kt++) {
        const int s = kt & (NSTAGE - 1);
        CP_WAIT2();
        __syncthreads();

        const float* As = smf + s * STG_U32;
        const float* Bs = As + 128 * PITCH;
#pragma unroll
        for (int kg = 0; kg < 2; kg++) {
            const int kA = kg * 8 + c;
            uint32_t af[4][4], bf[4][2];
#pragma unroll
            for (int mt = 0; mt < 4; mt++) {
                int m = warp_m + mt * 16 + r;
                af[mt][0] = __float_as_uint(As[m * PITCH + kA]);
                af[mt][1] = __float_as_uint(As[(m + 8) * PITCH + kA]);
                af[mt][2] = __float_as_uint(As[m * PITCH + kA + 4]);
                af[mt][3] = __float_as_uint(As[(m + 8) * PITCH + kA + 4]);
            }
#pragma unroll
            for (int nt = 0; nt < 4; nt++) {
                int n = warp_n + nt * 8 + r;
                bf[nt][0] = __float_as_uint(Bs[n * PITCH + kA]);
                bf[nt][1] = __float_as_uint(Bs[n * PITCH + kA + 4]);
            }
#pragma unroll
            for (int mt = 0; mt < 4; mt++)
#pragma unroll
                for (int nt = 0; nt < 4; nt++)
                    mma_tf32(acc[mt][nt], af[mt], bf[nt]);
        }
        __syncthreads();

        const int kn = kt + 3;
        if (kn < KT) {
            load_stage_f32(su + (kn & (NSTAGE - 1)) * STG_U32 * 4,
                           A, Bm, rowBase, colBase, K, kn, t);
            CP_COMMIT();
        }
    }

    epilogue(smf, acc, Cf, Cmask, Cbf, bias, Ntot, mode, sym, rowBase, colBase,
             warp_m, warp_n, r, c, t);
}

// ---------------- bf16 GEMM body (K-step 32, m16n8k16) -------------------------
__device__ __forceinline__ void load_stage_bf16(uint32_t sbase,
                                                const __nv_bfloat16* __restrict__ A,
                                                const __nv_bfloat16* __restrict__ Bm,
                                                int rowBase, int colBase, int K,
                                                int kt, int t) {
    const int k0 = kt * 32;
#pragma unroll
    for (int h = 0; h < 2; h++) {
        int idx = t + h * 256;
        int row = idx >> 2;
        int kc = idx & 3;                 // 16B chunk (8 bf16)
        CP_ASYNC16(sbase + (uint32_t)(row * PITCH + kc * 4) * 4,
                   A + (size_t)(rowBase + row) * K + k0 + kc * 8);
    }
#pragma unroll
    for (int h = 0; h < 2; h++) {
        int idx = t + h * 256;
        int row = idx >> 2;
        int kc = idx & 3;
        CP_ASYNC16(sbase + (uint32_t)(128 * PITCH + row * PITCH + kc * 4) * 4,
                   Bm + (size_t)(colBase + row) * K + k0 + kc * 8);
    }
}

__device__ __forceinline__ void gemm_body_bf16(
    float* smf, const __nv_bfloat16* __restrict__ A,
    const __nv_bfloat16* __restrict__ Bm,
    float* Cf, unsigned char* Cmask,
    int Ntot, int K, int mode, int sym, int rowBase, int colBase) {
    const uint32_t su = smem_u32(smf);
    const int t = threadIdx.x;
    const int wid = t >> 5;
    const int lane = t & 31;
    const int r = lane >> 2;
    const int c = lane & 3;
    const int warp_m = (wid & 1) * 64;
    const int warp_n = (wid >> 1) * 32;
    const int KT = K >> 5;                // 32 bf16 per k-step

    float acc[4][4][4];
#pragma unroll
    for (int mt = 0; mt < 4; mt++)
#pragma unroll
        for (int nt = 0; nt < 4; nt++)
#pragma unroll
            for (int q = 0; q < 4; q++) acc[mt][nt][q] = 0.f;

#pragma unroll
    for (int s = 0; s < 3; s++) {
        if (s < KT) {
            load_stage_bf16(su + s * STG_U32 * 4, A, Bm, rowBase, colBase, K, s, t);
            CP_COMMIT();
        }
    }

    for (int kt = 0; kt < KT; kt++) {
        const int s = kt & (NSTAGE - 1);
        CP_WAIT2();
        __syncthreads();

        const uint32_t* As = (const uint32_t*)smf + s * STG_U32;
        const uint32_t* Bs = As + 128 * PITCH;
#pragma unroll
        for (int kg = 0; kg < 2; kg++) {            // two k16 halves of the 32-chunk
            const int o = kg * 8 + c;               // u32 index within 16-u32 row
            uint32_t af[4][4], bfr[4][2];
#pragma unroll
            for (int mt = 0; mt < 4; mt++) {
                int m = warp_m + mt * 16 + r;
                af[mt][0] = As[m * PITCH + o];
                af[mt][1] = As[(m + 8) * PITCH + o];
                af[mt][2] = As[m * PITCH + o + 4];
                af[mt][3] = As[(m + 8) * PITCH + o + 4];
            }
#pragma unroll
            for (int nt = 0; nt < 4; nt++) {
                int n = warp_n + nt * 8 + r;
                bfr[nt][0] = Bs[n * PITCH + o];
                bfr[nt][1] = Bs[n * PITCH + o + 4];
            }
#pragma unroll
            for (int mt = 0; mt < 4; mt++)
#pragma unroll
                for (int nt = 0; nt < 4; nt++)
                    mma_bf16(acc[mt][nt], af[mt], bfr[nt]);
        }
        __syncthreads();

        const int kn = kt + 3;
        if (kn < KT) {
            load_stage_bf16(su + (kn & (NSTAGE - 1)) * STG_U32 * 4,
                            A, Bm, rowBase, colBase, K, kn, t);
            CP_COMMIT();
        }
    }

    epilogue(smf, acc, Cf, Cmask, nullptr, nullptr, Ntot, mode, sym,
             rowBase, colBase, warp_m, warp_n, r, c, t);
}

// ---------------- fused big-GEMM launch: sim + mask + attn (all bf16) ----------
__global__ void __launch_bounds__(256, 2)
fused_gemm(float* __restrict__ sim, unsigned char* __restrict__ maskp,
           float* __restrict__ attn) {
    extern __shared__ float smf[];
    int bid = blockIdx.x;

    if (bid < 2 * SIM_TILES) {
        int tt = (bid >= SIM_TILES) ? bid - SIM_TILES : bid;
        int x = (int)((sqrtf(8.f * tt + 1.f) - 1.f) * 0.5f);
        while ((x + 1) * (x + 2) / 2 <= tt) x++;
        while (x * (x + 1) / 2 > tt) x--;
        int bx = x;
        int by = tt - x * (x + 1) / 2;
        if (bid < SIM_TILES) {
            gemm_body_bf16(smf, g_znorm16, g_znorm16, sim, nullptr,
                           B_SZ, D_SZ, 0, 1, by * 128, bx * 128);
        } else {
            gemm_body_bf16(smf, g_bnorm16, g_bnorm16, nullptr, maskp,
                           B_SZ, D_SZ, 1, 1, by * 128, bx * 128);
        }
    } else {
        int l = bid - 2 * SIM_TILES;
        int bx = l & 31;
        int by = l >> 5;
        gemm_body_bf16(smf, g_f1z16, g_f2z16, attn, nullptr,
                       B_SZ, HID_SZ, 0, 0, by * 128, bx * 128);
    }
}

// ---------------- merged projections (tf32 in, bf16 out) ------------------------
__global__ void __launch_bounds__(256, 2)
proj_gemm(const float* __restrict__ zu,
          const float* __restrict__ f1w, const float* __restrict__ f1b,
          const float* __restrict__ f2w, const float* __restrict__ f2b) {
    extern __shared__ float smf[];
    int which = blockIdx.x >> 1;
    int colBase = (blockIdx.x & 1) * 128;
    const float* W = which ? f2w : f1w;
    const float* bias = which ? f2b : f1b;
    __nv_bfloat16* C = which ? g_f2z16 : g_f1z16;
    gemm_body_f32(smf, zu, W, nullptr, nullptr, C, bias, HID_SZ, D_SZ, 3, 0,
                  blockIdx.y * 128, colBase);
}

// ---------------- per-row loss: one block per row, one pass, vectorized ---------
__global__ void __launch_bounds__(256) row_loss_kernel() {
    const int i = blockIdx.x;
    const int t = threadIdx.x;
    const float4* s4p = (const float4*)(g_sim + (size_t)i * B_SZ);
    const uint4* m16p = (const uint4*)(g_mask + (size_t)i * B_SZ);
    const float* arow = g_attn + (size_t)i * B_SZ;

    float den = 0.f, m = -1e30f, Z = 0.f, T = 0.f, n = 0.f;

    const int j0 = t * 16;
    float sv[16];
    {
        float4 a0 = s4p[t * 4 + 0], a1 = s4p[t * 4 + 1];
        float4 a2 = s4p[t * 4 + 2], a3 = s4p[t * 4 + 3];
        sv[0] = a0.x; sv[1] = a0.y; sv[2] = a0.z; sv[3] = a0.w;
        sv[4] = a1.x; sv[5] = a1.y; sv[6] = a1.z; sv[7] = a1.w;
        sv[8] = a2.x; sv[9] = a2.y; sv[10] = a2.z; sv[11] = a2.w;
        sv[12] = a3.x; sv[13] = a3.y; sv[14] = a3.z; sv[15] = a3.w;
    }
    uint4 mw = m16p[t];

#pragma unroll
    for (int q = 0; q < 16; q++) {
        float e = ((q & 3) == 3) ? exp10s_poly(sv[q]) : __expf(sv[q] * INV_TAU);
        if (j0 + q != i) den += e;
    }

    uint32_t ws[4] = {mw.x, mw.y, mw.z, mw.w};
#pragma unroll
    for (int w4 = 0; w4 < 4; w4++) {
        uint32_t w = ws[w4];
        if (w) {
#pragma unroll
            for (int b = 0; b < 4; b++) {
                if ((w >> (8 * b)) & 0xffu) {
                    int q = w4 * 4 + b;
                    n += 1.0f;
                    float a = arow[j0 + q];
                    if (a > m) {
                        float sc = __expf(m - a);
                        Z *= sc; T *= sc; m = a;
                    }
                    float e = __expf(a - m);
                    Z += e;
                    T += e * sv[q];
                }
            }
        }
    }

    int lane = t & 31, wd = t >> 5;
#pragma unroll
    for (int o = 16; o > 0; o >>= 1) {
        float m2 = __shfl_down_sync(0xffffffffu, m, o);
        float Z2 = __shfl_down_sync(0xffffffffu, Z, o);
        float T2 = __shfl_down_sync(0xffffffffu, T, o);
        float d2 = __shfl_down_sync(0xffffffffu, den, o);
        float n2 = __shfl_down_sync(0xffffffffu, n, o);
        float M = fmaxf(m, m2);
        float s1 = __expf(m - M), s2 = __expf(m2 - M);
        Z = Z * s1 + Z2 * s2;
        T = T * s1 + T2 * s2;
        m = M;
        den += d2;
        n += n2;
    }
    __shared__ float sm_[8], sZ_[8], sT_[8], sd_[8], sn_[8];
    if (lane == 0) { sm_[wd] = m; sZ_[wd] = Z; sT_[wd] = T; sd_[wd] = den; sn_[wd] = n; }
    __syncthreads();
    if (wd == 0) {
        if (lane < 8) { m = sm_[lane]; Z = sZ_[lane]; T = sT_[lane]; den = sd_[lane]; n = sn_[lane]; }
        else { m = -1e30f; Z = 0.f; T = 0.f; den = 0.f; n = 0.f; }
#pragma unroll
        for (int o = 4; o > 0; o >>= 1) {
            float m2 = __shfl_down_sync(0xffffffffu, m, o);
            float Z2 = __shfl_down_sync(0xffffffffu, Z, o);
            float T2 = __shfl_down_sync(0xffffffffu, T, o);
            float d2 = __shfl_down_sync(0xffffffffu, den, o);
            float n2 = __shfl_down_sync(0xffffffffu, n, o);
            float M = fmaxf(m, m2);
            float s1 = __expf(m - M), s2 = __expf(m2 - M);
            Z = Z * s1 + Z2 * s2;
            T = T * s1 + T2 * s2;
            m = M;
            den += d2;
            n += n2;
        }
        if (lane == 0 && n > 0.5f) {
            float loss_i = logf(den + EPSF) - (T / Z) * INV_TAU;
            atomicAdd(&g_losssum, loss_i / n);
            atomicAdd(&g_nvalid, 1.0f);
        }
    }
}

// ---------------- finalize ------------------------------------------------------
__global__ void finalize_kernel(float* out) {
    const double invB = 1.0 / (double)B_SZ;
    double pold = 0.0, pnew = 0.0;
    for (int c = 0; c < NOLD_SZ; c++) pold += (double)g_meanprobs[c] * invB;
    for (int c = NOLD_SZ; c < NC_SZ; c++) pnew += (double)g_meanprobs[c] * invB;
    double loss_inter = pold * log(pold + 1e-8) + pnew * log(pnew + 1e-8) + log(2.0);
    double lo = 0.0;
    for (int c = 0; c < NOLD_SZ; c++) {
        double q = ((double)g_meanprobs[c] * invB) / (pold + 1e-8);
        lo += q * log(q + 1e-8);
    }
    lo += log((double)NOLD_SZ);
    double ln_ = 0.0;
    for (int c = NOLD_SZ; c < NC_SZ; c++) {
        double q = ((double)g_meanprobs[c] * invB) / (pnew + 1e-8);
        ln_ += q * log(q + 1e-8);
    }
    ln_ += log((double)NNEW_SZ);
    double le = loss_inter + lo + ln_;

    float nv = g_nvalid;
    float lc = (nv > 0.f) ? (g_losssum / fmaxf(nv, 1.0f)) : 0.f;
    out[0] = (float)le + lc;
}

// ---------------- launch --------------------------------------------------------
extern "C" void kernel_launch(void* const* d_in, const int* in_sizes, int n_in,
                              void* d_out, int out_size) {
    const float* z_u    = (const float*)d_in[0];
    const float* logits = (const float*)d_in[1];
    const float* base   = (const float*)d_in[4];
    const float* f1w    = (const float*)d_in[5];
    const float* f1b    = (const float*)d_in[6];
    const float* f2w    = (const float*)d_in[7];
    const float* f2b    = (const float*)d_in[8];
    float* out = (float*)d_out;
    (void)in_sizes; (void)n_in; (void)out_size;

    void *ps, *pa, *pm;
    cudaGetSymbolAddress(&ps, g_sim);
    cudaGetSymbolAddress(&pa, g_attn);
    cudaGetSymbolAddress(&pm, g_mask);

    cudaFuncSetAttribute(fused_gemm, cudaFuncAttributeMaxDynamicSharedMemorySize, SMEM_BYTES);
    cudaFuncSetAttribute(proj_gemm, cudaFuncAttributeMaxDynamicSharedMemorySize, SMEM_BYTES);

    zero_kernel<<<1, 256>>>();
    entropy_kernel<<<B_SZ / 8, 256>>>(logits);
    normalize_kernel<<<dim3(B_SZ, 2), 256>>>(z_u, base);

    // both projections in one launch (128 CTAs), outputs bf16
    proj_gemm<<<dim3(4, B_SZ / 128), 256, SMEM_BYTES>>>(z_u, f1w, f1b, f2w, f2b);

    // sim + mask + attn, all bf16, one launch (2080 CTAs)
    fused_gemm<<<2 * SIM_TILES + (B_SZ / 128) * (B_SZ / 128), 256, SMEM_BYTES>>>(
        (float*)ps, (unsigned char*)pm, (float*)pa);

    row_loss_kernel<<<B_SZ, 256>>>();
    finalize_kernel<<<1, 1>>>(out);
}